// round 10
// baseline (speedup 1.0000x reference)
#include <cuda_runtime.h>

#define NN 100000
#define EE 1600000
#define HH 64
#define TP 68        // tile pitch (floats)
#define DCAP 64      // per-node CSR bucket capacity (P(deg>64) ~ 1e-20)

#define NB_MLP 1563          // ceil(NN/64)
#define NB_SCAT 6250         // ceil(EE/256)
#define NB_TOT 7815          // 5*1563: bi%5==4 -> mlp, else scatter slot

typedef unsigned long long ull;

// ---------------- f32x2 packed-FMA helpers ----------------
__device__ __forceinline__ ull pk2(float lo, float hi) {
    ull r; asm("mov.b64 %0,{%1,%2};" : "=l"(r) : "f"(lo), "f"(hi)); return r;
}
__device__ __forceinline__ void fma2(ull& d, ull a, ull b) {
    asm("fma.rn.f32x2 %0,%1,%2,%0;" : "+l"(d) : "l"(a), "l"(b));
}
__device__ __forceinline__ float2 upk(ull v) {
    float lo, hi; asm("mov.b64 {%0,%1},%2;" : "=f"(lo), "=f"(hi) : "l"(v));
    return make_float2(lo, hi);
}
__device__ __forceinline__ float tanha(float x) {
    float r; asm("tanh.approx.f32 %0,%1;" : "=f"(r) : "f"(x)); return r;
}

// ---------------- scratch ----------------
__device__ float4 g_h4[NN * 16];
__device__ float4 g_agg4[NN * 16];
__device__ float4 g_acc4[NN * 16];
__device__ float4 g_xp4[NN * 16];
__device__ float2 g_di[NN];           // .x = rsqrt(deg) (k_dinv), .y = 1/(||h||+eps) (mlp)
__device__ int    g_cnt[NN];          // cursor during scatter; re-zeroed by k_gather
__device__ int    g_csr[NN * DCAP];   // fixed-bucket CSR

// ---------------- packed 64x64 GEMM cores ----------------
__device__ __forceinline__ void gemm_core(const float* __restrict__ inS,
                                          const float* __restrict__ wS,
                                          int rt, int jt, ull acc[4][2]) {
#pragma unroll
    for (int i = 0; i < 4; i++) { acc[i][0] = 0ull; acc[i][1] = 0ull; }
#pragma unroll 4
    for (int k0 = 0; k0 < 64; k0 += 4) {
        float4 xv0 = *(const float4*)(inS + (rt + 0) * TP + k0);
        float4 xv1 = *(const float4*)(inS + (rt + 1) * TP + k0);
        float4 xv2 = *(const float4*)(inS + (rt + 2) * TP + k0);
        float4 xv3 = *(const float4*)(inS + (rt + 3) * TP + k0);
#pragma unroll
        for (int kk = 0; kk < 4; kk++) {
            float4 wv = *(const float4*)(wS + ((k0 + kk) << 6) + jt);
            ull w0 = pk2(wv.x, wv.y), w1 = pk2(wv.z, wv.w);
            float x0 = kk == 0 ? xv0.x : kk == 1 ? xv0.y : kk == 2 ? xv0.z : xv0.w;
            float x1 = kk == 0 ? xv1.x : kk == 1 ? xv1.y : kk == 2 ? xv1.z : xv1.w;
            float x2 = kk == 0 ? xv2.x : kk == 1 ? xv2.y : kk == 2 ? xv2.z : xv2.w;
            float x3 = kk == 0 ? xv3.x : kk == 1 ? xv3.y : kk == 2 ? xv3.z : xv3.w;
            ull p;
            p = pk2(x0, x0); fma2(acc[0][0], p, w0); fma2(acc[0][1], p, w1);
            p = pk2(x1, x1); fma2(acc[1][0], p, w0); fma2(acc[1][1], p, w1);
            p = pk2(x2, x2); fma2(acc[2][0], p, w0); fma2(acc[2][1], p, w1);
            p = pk2(x3, x3); fma2(acc[3][0], p, w0); fma2(acc[3][1], p, w1);
        }
    }
}

// one input, two weight matrices
__device__ __forceinline__ void gemm_core_w2(const float* __restrict__ inS,
                                             const float* __restrict__ wA,
                                             const float* __restrict__ wB,
                                             int rt, int jt, ull a0[4][2], ull a1[4][2]) {
#pragma unroll
    for (int i = 0; i < 4; i++) { a0[i][0] = a0[i][1] = 0ull; a1[i][0] = a1[i][1] = 0ull; }
#pragma unroll 2
    for (int k0 = 0; k0 < 64; k0 += 4) {
        float4 xv0 = *(const float4*)(inS + (rt + 0) * TP + k0);
        float4 xv1 = *(const float4*)(inS + (rt + 1) * TP + k0);
        float4 xv2 = *(const float4*)(inS + (rt + 2) * TP + k0);
        float4 xv3 = *(const float4*)(inS + (rt + 3) * TP + k0);
#pragma unroll
        for (int kk = 0; kk < 4; kk++) {
            float4 wva = *(const float4*)(wA + ((k0 + kk) << 6) + jt);
            float4 wvb = *(const float4*)(wB + ((k0 + kk) << 6) + jt);
            ull wa0 = pk2(wva.x, wva.y), wa1 = pk2(wva.z, wva.w);
            ull wb0 = pk2(wvb.x, wvb.y), wb1 = pk2(wvb.z, wvb.w);
            float x0 = kk == 0 ? xv0.x : kk == 1 ? xv0.y : kk == 2 ? xv0.z : xv0.w;
            float x1 = kk == 0 ? xv1.x : kk == 1 ? xv1.y : kk == 2 ? xv1.z : xv1.w;
            float x2 = kk == 0 ? xv2.x : kk == 1 ? xv2.y : kk == 2 ? xv2.z : xv2.w;
            float x3 = kk == 0 ? xv3.x : kk == 1 ? xv3.y : kk == 2 ? xv3.z : xv3.w;
            ull p;
            p = pk2(x0, x0); fma2(a0[0][0], p, wa0); fma2(a0[0][1], p, wa1);
                             fma2(a1[0][0], p, wb0); fma2(a1[0][1], p, wb1);
            p = pk2(x1, x1); fma2(a0[1][0], p, wa0); fma2(a0[1][1], p, wa1);
                             fma2(a1[1][0], p, wb0); fma2(a1[1][1], p, wb1);
            p = pk2(x2, x2); fma2(a0[2][0], p, wa0); fma2(a0[2][1], p, wa1);
                             fma2(a1[2][0], p, wb0); fma2(a1[2][1], p, wb1);
            p = pk2(x3, x3); fma2(a0[3][0], p, wa0); fma2(a0[3][1], p, wa1);
                             fma2(a1[3][0], p, wb0); fma2(a1[3][1], p, wb1);
        }
    }
}

// two inputs, one weight matrix
__device__ __forceinline__ void gemm_core2(const float* __restrict__ in0,
                                           const float* __restrict__ in1,
                                           const float* __restrict__ wS,
                                           int rt, int jt, ull a0[4][2], ull a1[4][2]) {
#pragma unroll
    for (int i = 0; i < 4; i++) { a0[i][0] = a0[i][1] = 0ull; a1[i][0] = a1[i][1] = 0ull; }
#pragma unroll 2
    for (int k0 = 0; k0 < 64; k0 += 4) {
        float4 u0 = *(const float4*)(in0 + (rt + 0) * TP + k0);
        float4 u1 = *(const float4*)(in0 + (rt + 1) * TP + k0);
        float4 u2 = *(const float4*)(in0 + (rt + 2) * TP + k0);
        float4 u3 = *(const float4*)(in0 + (rt + 3) * TP + k0);
        float4 v0 = *(const float4*)(in1 + (rt + 0) * TP + k0);
        float4 v1 = *(const float4*)(in1 + (rt + 1) * TP + k0);
        float4 v2 = *(const float4*)(in1 + (rt + 2) * TP + k0);
        float4 v3 = *(const float4*)(in1 + (rt + 3) * TP + k0);
#pragma unroll
        for (int kk = 0; kk < 4; kk++) {
            float4 wv = *(const float4*)(wS + ((k0 + kk) << 6) + jt);
            ull w0 = pk2(wv.x, wv.y), w1 = pk2(wv.z, wv.w);
            float s0 = kk == 0 ? u0.x : kk == 1 ? u0.y : kk == 2 ? u0.z : u0.w;
            float s1 = kk == 0 ? u1.x : kk == 1 ? u1.y : kk == 2 ? u1.z : u1.w;
            float s2 = kk == 0 ? u2.x : kk == 1 ? u2.y : kk == 2 ? u2.z : u2.w;
            float s3 = kk == 0 ? u3.x : kk == 1 ? u3.y : kk == 2 ? u3.z : u3.w;
            float t0 = kk == 0 ? v0.x : kk == 1 ? v0.y : kk == 2 ? v0.z : v0.w;
            float t1 = kk == 0 ? v1.x : kk == 1 ? v1.y : kk == 2 ? v1.z : v1.w;
            float t2 = kk == 0 ? v2.x : kk == 1 ? v2.y : kk == 2 ? v2.z : v2.w;
            float t3 = kk == 0 ? v3.x : kk == 1 ? v3.y : kk == 2 ? v3.z : v3.w;
            ull p;
            p = pk2(s0, s0); fma2(a0[0][0], p, w0); fma2(a0[0][1], p, w1);
            p = pk2(s1, s1); fma2(a0[1][0], p, w0); fma2(a0[1][1], p, w1);
            p = pk2(s2, s2); fma2(a0[2][0], p, w0); fma2(a0[2][1], p, w1);
            p = pk2(s3, s3); fma2(a0[3][0], p, w0); fma2(a0[3][1], p, w1);
            p = pk2(t0, t0); fma2(a1[0][0], p, w0); fma2(a1[0][1], p, w1);
            p = pk2(t1, t1); fma2(a1[1][0], p, w0); fma2(a1[1][1], p, w1);
            p = pk2(t2, t2); fma2(a1[2][0], p, w0); fma2(a1[2][1], p, w1);
            p = pk2(t3, t3); fma2(a1[3][0], p, w0); fma2(a1[3][1], p, w1);
        }
    }
}

// weight prefetch helpers
__device__ __forceinline__ void wload(const float* __restrict__ w, int t, float4 wr[4]) {
#pragma unroll
    for (int i = 0; i < 4; i++) wr[i] = ((const float4*)w)[t + i * 256];
}
__device__ __forceinline__ void wstore(float* ws, int t, const float4 wr[4]) {
#pragma unroll
    for (int i = 0; i < 4; i++) ((float4*)ws)[t + i * 256] = wr[i];
}

// ---------------- MLP block body (no g_cnt access — scatter runs concurrently) ---
__device__ void mlp_block(int mb,
    const float* __restrict__ x,
    const float* __restrict__ w1, const float* __restrict__ b1,
    const float* __restrict__ w2, const float* __restrict__ b2,
    const float* __restrict__ w3, const float* __restrict__ b3,
    const float* __restrict__ wx, const float* __restrict__ bx,
    float* sm) {
    float* wsA = sm;
    float* wsB = sm + 4096;
    float* bs  = sm + 8192;
    float* tA  = sm + 8448;
    float* tB  = sm + 12800;
    int t = threadIdx.x;
    const int jt = (t & 15) * 4;
    const int rt = (t >> 4) * 4;
    int n0 = mb * 64;

    if (t < 64) { bs[t] = b1[t]; bs[64 + t] = b2[t]; bs[128 + t] = b3[t]; bs[192 + t] = bx[t]; }
    for (int i = t; i < 1024; i += 256) {
        int r = i >> 4, s4 = i & 15;
        int n = n0 + r;
        float4 v = (n < NN) ? *(const float4*)(x + n * 64 + s4 * 4) : make_float4(0, 0, 0, 0);
        *(float4*)(tA + r * TP + s4 * 4) = v;
        ((float4*)wsA)[i] = ((const float4*)w1)[i];
    }
    __syncthreads();

    ull acc[4][2];
    float4 wr[4];
    wload(w2, t, wr);
    gemm_core(tA, wsA, rt, jt, acc);
#pragma unroll
    for (int i = 0; i < 4; i++) {
        float2 p0 = upk(acc[i][0]), p1 = upk(acc[i][1]);
        tB[(rt + i) * TP + jt + 0] = fmaxf(p0.x + bs[jt + 0], 0.f);
        tB[(rt + i) * TP + jt + 1] = fmaxf(p0.y + bs[jt + 1], 0.f);
        tB[(rt + i) * TP + jt + 2] = fmaxf(p1.x + bs[jt + 2], 0.f);
        tB[(rt + i) * TP + jt + 3] = fmaxf(p1.y + bs[jt + 3], 0.f);
    }
    wstore(wsB, t, wr);
    __syncthreads();
    wload(w3, t, wr);
    gemm_core(tB, wsB, rt, jt, acc);
#pragma unroll
    for (int i = 0; i < 4; i++) {
        float2 p0 = upk(acc[i][0]), p1 = upk(acc[i][1]);
        tA[(rt + i) * TP + jt + 0] = fmaxf(p0.x + bs[64 + jt + 0], 0.f);
        tA[(rt + i) * TP + jt + 1] = fmaxf(p0.y + bs[64 + jt + 1], 0.f);
        tA[(rt + i) * TP + jt + 2] = fmaxf(p1.x + bs[64 + jt + 2], 0.f);
        tA[(rt + i) * TP + jt + 3] = fmaxf(p1.y + bs[64 + jt + 3], 0.f);
    }
    wstore(wsA, t, wr);
    __syncthreads();
    wload(wx, t, wr);
    gemm_core(tA, wsA, rt, jt, acc);
#pragma unroll
    for (int i = 0; i < 4; i++) {
        float2 p0 = upk(acc[i][0]), p1 = upk(acc[i][1]);
        float h0 = p0.x + bs[128 + jt + 0];
        float h1 = p0.y + bs[128 + jt + 1];
        float h2 = p1.x + bs[128 + jt + 2];
        float h3 = p1.y + bs[128 + jt + 3];
        tB[(rt + i) * TP + jt + 0] = h0;
        tB[(rt + i) * TP + jt + 1] = h1;
        tB[(rt + i) * TP + jt + 2] = h2;
        tB[(rt + i) * TP + jt + 3] = h3;
        int n = n0 + rt + i;
        if (n < NN) g_h4[n * 16 + (jt >> 2)] = make_float4(h0, h1, h2, h3);
    }
    wstore(wsB, t, wr);
    __syncthreads();
    if (t < 64) {
        int n = n0 + t;
        if (n < NN) {
            float ss = 0.f;
#pragma unroll 8
            for (int k = 0; k < 64; k++) { float v = tB[t * TP + k]; ss = fmaf(v, v, ss); }
            g_di[n].y = 1.f / (sqrtf(ss) + 1e-12f);   // .x written later by k_dinv
        }
    }
    gemm_core(tB, wsB, rt, jt, acc);
#pragma unroll
    for (int i = 0; i < 4; i++) {
        int n = n0 + rt + i;
        if (n < NN) {
            float2 p0 = upk(acc[i][0]), p1 = upk(acc[i][1]);
            g_xp4[n * 16 + (jt >> 2)] = make_float4(
                tanha(p0.x + bs[192 + jt + 0]), tanha(p0.y + bs[192 + jt + 1]),
                tanha(p1.x + bs[192 + jt + 2]), tanha(p1.y + bs[192 + jt + 3]));
        }
    }
}

// ---------------- fused scatter + MLP (block-role interleaving, 4:1) -------------
#define SMEM_MLP_FLOATS 17152
__global__ void __launch_bounds__(256) k_fused(
    const int* __restrict__ ei,
    const float* __restrict__ x,
    const float* __restrict__ w1, const float* __restrict__ b1,
    const float* __restrict__ w2, const float* __restrict__ b2,
    const float* __restrict__ w3, const float* __restrict__ b3,
    const float* __restrict__ wx, const float* __restrict__ bx) {
    extern __shared__ float sm[];
    int bi = blockIdx.x;
    if ((bi % 5) == 4) {
        mlp_block(bi / 5, x, w1, b1, w2, b2, w3, b3, wx, bx, sm);
    } else {
        int si = (bi / 5) * 4 + (bi % 5);
        if (si < NB_SCAT) {
            int e = si * 256 + threadIdx.x;
            if (e < EE) {
                int r = ei[e];
                int c = ei[EE + e];
                int p = atomicAdd(&g_cnt[c], 1);
                if (p < DCAP) g_csr[(c << 6) + p] = r;
            }
        }
    }
}

// ---------------- dinv (needs final g_cnt; runs after k_fused) ----------------
__global__ void k_dinv() {
    int i = blockIdx.x * blockDim.x + threadIdx.x;
    if (i < NN) g_di[i].x = rsqrtf((float)(g_cnt[i] + 1));
}

// ---------------- CSR pull gather (unchanged) ----------------
__global__ void __launch_bounds__(256) k_gather(const float* __restrict__ betap) {
    int warp = (blockIdx.x * 256 + threadIdx.x) >> 5;
    if (warp >= NN) return;
    int c = warp;
    int lane = threadIdx.x & 31;
    int sub = lane >> 3;
    int sl  = lane & 7;
    float beta = *betap;
    float4 hc0 = g_h4[c * 16 + sl * 2];
    float4 hc1 = g_h4[c * 16 + sl * 2 + 1];
    float2 dic = g_di[c];

    float dps = hc0.x * hc0.x + hc0.y * hc0.y + hc0.z * hc0.z + hc0.w * hc0.w
              + hc1.x * hc1.x + hc1.y * hc1.y + hc1.z * hc1.z + hc1.w * hc1.w;
    dps += __shfl_xor_sync(0xFFFFFFFFu, dps, 1);
    dps += __shfl_xor_sync(0xFFFFFFFFu, dps, 2);
    dps += __shfl_xor_sync(0xFFFFFFFFu, dps, 4);
    float evs = __expf(beta * dps * dic.y * dic.y);
    float4 agg0, agg1, acc0, acc1;
    float s;
    if (sub == 0) {
        agg0 = make_float4(dic.x * hc0.x, dic.x * hc0.y, dic.x * hc0.z, dic.x * hc0.w);
        agg1 = make_float4(dic.x * hc1.x, dic.x * hc1.y, dic.x * hc1.z, dic.x * hc1.w);
        acc0 = make_float4(evs * hc0.x, evs * hc0.y, evs * hc0.z, evs * hc0.w);
        acc1 = make_float4(evs * hc1.x, evs * hc1.y, evs * hc1.z, evs * hc1.w);
        s = evs;
    } else {
        agg0 = agg1 = acc0 = acc1 = make_float4(0.f, 0.f, 0.f, 0.f);
        s = 0.f;
    }

    int beg = c << 6;
    int cnt = min(g_cnt[c], DCAP);
    int T = (cnt + 3) >> 2;
    bool v0 = (sub < cnt);
    int r0 = v0 ? g_csr[beg + sub] : c;
    float4 a0 = g_h4[r0 * 16 + sl * 2];
    float4 b0 = g_h4[r0 * 16 + sl * 2 + 1];
    float2 d0 = g_di[r0];
    for (int it = 0; it < T; it++) {
        int nx = 4 * (it + 1) + sub;
        bool vn = (nx < cnt);
        int rn = vn ? g_csr[beg + nx] : c;
        float4 an = g_h4[rn * 16 + sl * 2];
        float4 bn = g_h4[rn * 16 + sl * 2 + 1];
        float2 dn = g_di[rn];

        float dp = a0.x * hc0.x + a0.y * hc0.y + a0.z * hc0.z + a0.w * hc0.w
                 + b0.x * hc1.x + b0.y * hc1.y + b0.z * hc1.z + b0.w * hc1.w;
        dp += __shfl_xor_sync(0xFFFFFFFFu, dp, 1);
        dp += __shfl_xor_sync(0xFFFFFFFFu, dp, 2);
        dp += __shfl_xor_sync(0xFFFFFFFFu, dp, 4);
        float ev = v0 ? __expf(beta * dp * d0.y * dic.y) : 0.f;
        float w  = v0 ? d0.x : 0.f;
        agg0.x = fmaf(w, a0.x, agg0.x); agg0.y = fmaf(w, a0.y, agg0.y);
        agg0.z = fmaf(w, a0.z, agg0.z); agg0.w = fmaf(w, a0.w, agg0.w);
        agg1.x = fmaf(w, b0.x, agg1.x); agg1.y = fmaf(w, b0.y, agg1.y);
        agg1.z = fmaf(w, b0.z, agg1.z); agg1.w = fmaf(w, b0.w, agg1.w);
        acc0.x = fmaf(ev, a0.x, acc0.x); acc0.y = fmaf(ev, a0.y, acc0.y);
        acc0.z = fmaf(ev, a0.z, acc0.z); acc0.w = fmaf(ev, a0.w, acc0.w);
        acc1.x = fmaf(ev, b0.x, acc1.x); acc1.y = fmaf(ev, b0.y, acc1.y);
        acc1.z = fmaf(ev, b0.z, acc1.z); acc1.w = fmaf(ev, b0.w, acc1.w);
        s += ev;
        v0 = vn; r0 = rn; a0 = an; b0 = bn; d0 = dn;
    }
#pragma unroll
    for (int d = 8; d <= 16; d <<= 1) {
        agg0.x += __shfl_xor_sync(0xFFFFFFFFu, agg0.x, d);
        agg0.y += __shfl_xor_sync(0xFFFFFFFFu, agg0.y, d);
        agg0.z += __shfl_xor_sync(0xFFFFFFFFu, agg0.z, d);
        agg0.w += __shfl_xor_sync(0xFFFFFFFFu, agg0.w, d);
        agg1.x += __shfl_xor_sync(0xFFFFFFFFu, agg1.x, d);
        agg1.y += __shfl_xor_sync(0xFFFFFFFFu, agg1.y, d);
        agg1.z += __shfl_xor_sync(0xFFFFFFFFu, agg1.z, d);
        agg1.w += __shfl_xor_sync(0xFFFFFFFFu, agg1.w, d);
        acc0.x += __shfl_xor_sync(0xFFFFFFFFu, acc0.x, d);
        acc0.y += __shfl_xor_sync(0xFFFFFFFFu, acc0.y, d);
        acc0.z += __shfl_xor_sync(0xFFFFFFFFu, acc0.z, d);
        acc0.w += __shfl_xor_sync(0xFFFFFFFFu, acc0.w, d);
        acc1.x += __shfl_xor_sync(0xFFFFFFFFu, acc1.x, d);
        acc1.y += __shfl_xor_sync(0xFFFFFFFFu, acc1.y, d);
        acc1.z += __shfl_xor_sync(0xFFFFFFFFu, acc1.z, d);
        acc1.w += __shfl_xor_sync(0xFFFFFFFFu, acc1.w, d);
        s += __shfl_xor_sync(0xFFFFFFFFu, s, d);
    }
    if (sub == 0) {
        float invs = 1.f / s;
        g_agg4[c * 16 + sl * 2] = make_float4(dic.x * agg0.x, dic.x * agg0.y, dic.x * agg0.z, dic.x * agg0.w);
        g_agg4[c * 16 + sl * 2 + 1] = make_float4(dic.x * agg1.x, dic.x * agg1.y, dic.x * agg1.z, dic.x * agg1.w);
        g_acc4[c * 16 + sl * 2] = make_float4(invs * acc0.x, invs * acc0.y, invs * acc0.z, invs * acc0.w);
        g_acc4[c * 16 + sl * 2 + 1] = make_float4(invs * acc1.x, invs * acc1.y, invs * acc1.z, invs * acc1.w);
    }
    if (lane == 0) g_cnt[c] = 0;
}

// ---------------- fused filters + attention fusion + classifier ----------------
#define SMEM_FIN_FLOATS 21704
__global__ void __launch_bounds__(256) k_final(
    const float* __restrict__ wg1, const float* __restrict__ bg1,
    const float* __restrict__ wg2, const float* __restrict__ bg2,
    const float* __restrict__ wf,  const float* __restrict__ bf,
    const float* __restrict__ wc,  const float* __restrict__ bc,
    float* __restrict__ out) {
    extern __shared__ float sm[];
    float* wsA  = sm;
    float* wsB  = sm + 4096;
    float* wcs  = sm + 8192;
    float* bs   = sm + 8448;
    float* aggS = sm + 8648;
    float* f0S  = sm + 13000;
    float* f1S  = sm + 17352;
    int t = threadIdx.x;
    const int jt = (t & 15) * 4;
    const int rt = (t >> 4) * 4;
    int n0 = blockIdx.x * 64;

    if (t < 256) wcs[t] = wc[t];
    if (t < 64) { bs[t] = bg1[t]; bs[64 + t] = bg2[t]; bs[128 + t] = bf[t]; }
    if (t < 2) bs[192 + t] = bc[t];
    const float* agg = (const float*)g_agg4;
    for (int i = t; i < 1024; i += 256) {
        int r = i >> 4, s4 = i & 15;
        int n = n0 + r;
        float4 v = (n < NN) ? *(const float4*)(agg + n * 64 + s4 * 4) : make_float4(0, 0, 0, 0);
        *(float4*)(aggS + r * TP + s4 * 4) = v;
        ((float4*)wsA)[i] = ((const float4*)wg1)[i];
        ((float4*)wsB)[i] = ((const float4*)wg2)[i];
    }
    __syncthreads();

    ull a0[4][2], a1[4][2];
    float4 wr[4];
    float2 f0r[4][2], f1r[4][2];
    wload(wf, t, wr);
    gemm_core_w2(aggS, wsA, wsB, rt, jt, a0, a1);
    __syncthreads();
#pragma unroll
    for (int i = 0; i < 4; i++) {
        float2 p0 = upk(a0[i][0]), p1 = upk(a0[i][1]);
        float2 q0 = upk(a1[i][0]), q1 = upk(a1[i][1]);
        f0r[i][0] = make_float2(p0.x + bs[jt + 0], p0.y + bs[jt + 1]);
        f0r[i][1] = make_float2(p1.x + bs[jt + 2], p1.y + bs[jt + 3]);
        f1r[i][0] = make_float2(q0.x + bs[64 + jt + 0], q0.y + bs[64 + jt + 1]);
        f1r[i][1] = make_float2(q1.x + bs[64 + jt + 2], q1.y + bs[64 + jt + 3]);
        f0S[(rt + i) * TP + jt + 0] = f0r[i][0].x;
        f0S[(rt + i) * TP + jt + 1] = f0r[i][0].y;
        f0S[(rt + i) * TP + jt + 2] = f0r[i][1].x;
        f0S[(rt + i) * TP + jt + 3] = f0r[i][1].y;
        f1S[(rt + i) * TP + jt + 0] = f1r[i][0].x;
        f1S[(rt + i) * TP + jt + 1] = f1r[i][0].y;
        f1S[(rt + i) * TP + jt + 2] = f1r[i][1].x;
        f1S[(rt + i) * TP + jt + 3] = f1r[i][1].y;
    }
    wstore(wsA, t, wr);
    __syncthreads();
    gemm_core2(f0S, f1S, wsA, rt, jt, a0, a1);
    float p0a[4], p1a[4];
    const float* xp = (const float*)g_xp4;
#pragma unroll
    for (int i = 0; i < 4; i++) {
        int n = n0 + rt + i;
        float4 xv = (n < NN) ? *(const float4*)(xp + n * 64 + jt) : make_float4(0, 0, 0, 0);
        float2 q0 = upk(a0[i][0]), q1 = upk(a0[i][1]);
        float2 r0 = upk(a1[i][0]), r1 = upk(a1[i][1]);
        float h00 = tanha(q0.x + bs[128 + jt + 0]);
        float h01 = tanha(q0.y + bs[128 + jt + 1]);
        float h02 = tanha(q1.x + bs[128 + jt + 2]);
        float h03 = tanha(q1.y + bs[128 + jt + 3]);
        float h10 = tanha(r0.x + bs[128 + jt + 0]);
        float h11 = tanha(r0.y + bs[128 + jt + 1]);
        float h12 = tanha(r1.x + bs[128 + jt + 2]);
        float h13 = tanha(r1.y + bs[128 + jt + 3]);
        p0a[i] = h00 * xv.x + h01 * xv.y + h02 * xv.z + h03 * xv.w;
        p1a[i] = h10 * xv.x + h11 * xv.y + h12 * xv.z + h13 * xv.w;
    }
#pragma unroll
    for (int d = 1; d <= 8; d <<= 1) {
#pragma unroll
        for (int i = 0; i < 4; i++) {
            p0a[i] += __shfl_xor_sync(0xFFFFFFFFu, p0a[i], d);
            p1a[i] += __shfl_xor_sync(0xFFFFFFFFu, p1a[i], d);
        }
    }
    float sc0r[4], sc1r[4];
#pragma unroll
    for (int i = 0; i < 4; i++) {
        float mx = fmaxf(p0a[i], p1a[i]);
        float e0 = __expf(p0a[i] - mx), e1 = __expf(p1a[i] - mx);
        float inv = 1.f / (e0 + e1);
        sc0r[i] = e0 * inv;
        sc1r[i] = e1 * inv;
    }
    const float* acc1g = (const float*)g_acc4;
    float y0[4], y1[4];
#pragma unroll
    for (int i = 0; i < 4; i++) {
        int n = n0 + rt + i;
        y0[i] = 0.f; y1[i] = 0.f;
        if (n < NN) {
            float4 hv = *(const float4*)(acc1g + n * 64 + jt);
            float fr[4] = {
                sc0r[i] * f0r[i][0].x + sc1r[i] * f1r[i][0].x,
                sc0r[i] * f0r[i][0].y + sc1r[i] * f1r[i][0].y,
                sc0r[i] * f0r[i][1].x + sc1r[i] * f1r[i][1].x,
                sc0r[i] * f0r[i][1].y + sc1r[i] * f1r[i][1].y };
            float h1v[4] = {hv.x, hv.y, hv.z, hv.w};
#pragma unroll
            for (int q = 0; q < 4; q++) {
                int j = jt + q;
                y0[i] += fr[q] * wcs[j * 2 + 0] + h1v[q] * wcs[(64 + j) * 2 + 0];
                y1[i] += fr[q] * wcs[j * 2 + 1] + h1v[q] * wcs[(64 + j) * 2 + 1];
            }
        }
    }
#pragma unroll
    for (int d = 1; d <= 8; d <<= 1) {
#pragma unroll
        for (int i = 0; i < 4; i++) {
            y0[i] += __shfl_xor_sync(0xFFFFFFFFu, y0[i], d);
            y1[i] += __shfl_xor_sync(0xFFFFFFFFu, y1[i], d);
        }
    }
    if ((t & 15) == 0) {
#pragma unroll
        for (int i = 0; i < 4; i++) {
            int n = n0 + rt + i;
            if (n < NN) {
                out[n * 2 + 0] = y0[i] + bs[192];
                out[n * 2 + 1] = y1[i] + bs[193];
            }
        }
    }
}

// ---------------- launch: 4 kernels ----------------
extern "C" void kernel_launch(void* const* d_in, const int* in_sizes, int n_in,
                              void* d_out, int out_size) {
    const float* x   = (const float*)d_in[0];
    const int*   ei  = (const int*)d_in[1];
    const float* w1  = (const float*)d_in[2];
    const float* b1  = (const float*)d_in[3];
    const float* w2  = (const float*)d_in[4];
    const float* b2  = (const float*)d_in[5];
    const float* w3  = (const float*)d_in[6];
    const float* b3  = (const float*)d_in[7];
    const float* wg1 = (const float*)d_in[8];
    const float* bg1 = (const float*)d_in[9];
    const float* wg2 = (const float*)d_in[10];
    const float* bg2 = (const float*)d_in[11];
    const float* beta= (const float*)d_in[12];
    const float* wf  = (const float*)d_in[13];
    const float* bf  = (const float*)d_in[14];
    const float* wx  = (const float*)d_in[15];
    const float* bx  = (const float*)d_in[16];
    const float* wc  = (const float*)d_in[17];
    const float* bc  = (const float*)d_in[18];
    float* out = (float*)d_out;

    cudaFuncSetAttribute(k_fused, cudaFuncAttributeMaxDynamicSharedMemorySize, SMEM_MLP_FLOATS * 4);
    cudaFuncSetAttribute(k_final, cudaFuncAttributeMaxDynamicSharedMemorySize, SMEM_FIN_FLOATS * 4);

    k_fused<<<NB_TOT, 256, SMEM_MLP_FLOATS * 4>>>(ei, x, w1, b1, w2, b2, w3, b3, wx, bx);
    k_dinv<<<(NN + 255) / 256, 256>>>();
    k_gather<<<(NN * 32 + 255) / 256, 256>>>(beta);
    k_final<<<(NN + 63) / 64, 256, SMEM_FIN_FLOATS * 4>>>(wg1, bg1, wg2, bg2, wf, bf, wc, bc, out);
}

// round 11
// speedup vs baseline: 1.0451x; 1.0451x over previous
#include <cuda_runtime.h>

#define NN 100000
#define EE 1600000
#define HH 64
#define TP 68        // tile pitch (floats)
#define DCAP 64      // per-node CSR bucket capacity (P(deg>64) ~ 1e-20)

typedef unsigned long long ull;

// ---------------- f32x2 packed-FMA helpers ----------------
__device__ __forceinline__ ull pk2(float lo, float hi) {
    ull r; asm("mov.b64 %0,{%1,%2};" : "=l"(r) : "f"(lo), "f"(hi)); return r;
}
__device__ __forceinline__ void fma2(ull& d, ull a, ull b) {
    asm("fma.rn.f32x2 %0,%1,%2,%0;" : "+l"(d) : "l"(a), "l"(b));
}
__device__ __forceinline__ float2 upk(ull v) {
    float lo, hi; asm("mov.b64 {%0,%1},%2;" : "=f"(lo), "=f"(hi) : "l"(v));
    return make_float2(lo, hi);
}
__device__ __forceinline__ float tanha(float x) {
    float r; asm("tanh.approx.f32 %0,%1;" : "=f"(r) : "f"(x)); return r;
}

// ---------------- scratch ----------------
__device__ float4 g_h4[NN * 16];
__device__ float4 g_agg4[NN * 16];
__device__ float4 g_acc4[NN * 16];
__device__ float4 g_xp4[NN * 16];
__device__ float2 g_di[NN];           // .x = rsqrt(deg), .y = 1/(||h||+eps)
__device__ int    g_cnt[NN];          // cursor during scatter; re-zeroed by k_gather
__device__ int    g_csr[NN * DCAP];   // fixed-bucket CSR

// ---------------- single-pass CSR scatter (PDL primary) ----------------
__global__ void k_scatter(const int* __restrict__ ei) {
    cudaTriggerProgrammaticLaunchCompletion();   // let k_mlp start now
    int e = blockIdx.x * blockDim.x + threadIdx.x;
    if (e < EE) {
        int r = ei[e];
        int c = ei[EE + e];
        int p = atomicAdd(&g_cnt[c], 1);
        if (p < DCAP) g_csr[(c << 6) + p] = r;
    }
}

// ---------------- packed 64x64 GEMM cores ----------------
__device__ __forceinline__ void gemm_core(const float* __restrict__ inS,
                                          const float* __restrict__ wS,
                                          int rt, int jt, ull acc[4][2]) {
#pragma unroll
    for (int i = 0; i < 4; i++) { acc[i][0] = 0ull; acc[i][1] = 0ull; }
#pragma unroll 4
    for (int k0 = 0; k0 < 64; k0 += 4) {
        float4 xv0 = *(const float4*)(inS + (rt + 0) * TP + k0);
        float4 xv1 = *(const float4*)(inS + (rt + 1) * TP + k0);
        float4 xv2 = *(const float4*)(inS + (rt + 2) * TP + k0);
        float4 xv3 = *(const float4*)(inS + (rt + 3) * TP + k0);
#pragma unroll
        for (int kk = 0; kk < 4; kk++) {
            float4 wv = *(const float4*)(wS + ((k0 + kk) << 6) + jt);
            ull w0 = pk2(wv.x, wv.y), w1 = pk2(wv.z, wv.w);
            float x0 = kk == 0 ? xv0.x : kk == 1 ? xv0.y : kk == 2 ? xv0.z : xv0.w;
            float x1 = kk == 0 ? xv1.x : kk == 1 ? xv1.y : kk == 2 ? xv1.z : xv1.w;
            float x2 = kk == 0 ? xv2.x : kk == 1 ? xv2.y : kk == 2 ? xv2.z : xv2.w;
            float x3 = kk == 0 ? xv3.x : kk == 1 ? xv3.y : kk == 2 ? xv3.z : xv3.w;
            ull p;
            p = pk2(x0, x0); fma2(acc[0][0], p, w0); fma2(acc[0][1], p, w1);
            p = pk2(x1, x1); fma2(acc[1][0], p, w0); fma2(acc[1][1], p, w1);
            p = pk2(x2, x2); fma2(acc[2][0], p, w0); fma2(acc[2][1], p, w1);
            p = pk2(x3, x3); fma2(acc[3][0], p, w0); fma2(acc[3][1], p, w1);
        }
    }
}

// one input, two weight matrices
__device__ __forceinline__ void gemm_core_w2(const float* __restrict__ inS,
                                             const float* __restrict__ wA,
                                             const float* __restrict__ wB,
                                             int rt, int jt, ull a0[4][2], ull a1[4][2]) {
#pragma unroll
    for (int i = 0; i < 4; i++) { a0[i][0] = a0[i][1] = 0ull; a1[i][0] = a1[i][1] = 0ull; }
#pragma unroll 2
    for (int k0 = 0; k0 < 64; k0 += 4) {
        float4 xv0 = *(const float4*)(inS + (rt + 0) * TP + k0);
        float4 xv1 = *(const float4*)(inS + (rt + 1) * TP + k0);
        float4 xv2 = *(const float4*)(inS + (rt + 2) * TP + k0);
        float4 xv3 = *(const float4*)(inS + (rt + 3) * TP + k0);
#pragma unroll
        for (int kk = 0; kk < 4; kk++) {
            float4 wva = *(const float4*)(wA + ((k0 + kk) << 6) + jt);
            float4 wvb = *(const float4*)(wB + ((k0 + kk) << 6) + jt);
            ull wa0 = pk2(wva.x, wva.y), wa1 = pk2(wva.z, wva.w);
            ull wb0 = pk2(wvb.x, wvb.y), wb1 = pk2(wvb.z, wvb.w);
            float x0 = kk == 0 ? xv0.x : kk == 1 ? xv0.y : kk == 2 ? xv0.z : xv0.w;
            float x1 = kk == 0 ? xv1.x : kk == 1 ? xv1.y : kk == 2 ? xv1.z : xv1.w;
            float x2 = kk == 0 ? xv2.x : kk == 1 ? xv2.y : kk == 2 ? xv2.z : xv2.w;
            float x3 = kk == 0 ? xv3.x : kk == 1 ? xv3.y : kk == 2 ? xv3.z : xv3.w;
            ull p;
            p = pk2(x0, x0); fma2(a0[0][0], p, wa0); fma2(a0[0][1], p, wa1);
                             fma2(a1[0][0], p, wb0); fma2(a1[0][1], p, wb1);
            p = pk2(x1, x1); fma2(a0[1][0], p, wa0); fma2(a0[1][1], p, wa1);
                             fma2(a1[1][0], p, wb0); fma2(a1[1][1], p, wb1);
            p = pk2(x2, x2); fma2(a0[2][0], p, wa0); fma2(a0[2][1], p, wa1);
                             fma2(a1[2][0], p, wb0); fma2(a1[2][1], p, wb1);
            p = pk2(x3, x3); fma2(a0[3][0], p, wa0); fma2(a0[3][1], p, wa1);
                             fma2(a1[3][0], p, wb0); fma2(a1[3][1], p, wb1);
        }
    }
}

// two inputs, one weight matrix
__device__ __forceinline__ void gemm_core2(const float* __restrict__ in0,
                                           const float* __restrict__ in1,
                                           const float* __restrict__ wS,
                                           int rt, int jt, ull a0[4][2], ull a1[4][2]) {
#pragma unroll
    for (int i = 0; i < 4; i++) { a0[i][0] = a0[i][1] = 0ull; a1[i][0] = a1[i][1] = 0ull; }
#pragma unroll 2
    for (int k0 = 0; k0 < 64; k0 += 4) {
        float4 u0 = *(const float4*)(in0 + (rt + 0) * TP + k0);
        float4 u1 = *(const float4*)(in0 + (rt + 1) * TP + k0);
        float4 u2 = *(const float4*)(in0 + (rt + 2) * TP + k0);
        float4 u3 = *(const float4*)(in0 + (rt + 3) * TP + k0);
        float4 v0 = *(const float4*)(in1 + (rt + 0) * TP + k0);
        float4 v1 = *(const float4*)(in1 + (rt + 1) * TP + k0);
        float4 v2 = *(const float4*)(in1 + (rt + 2) * TP + k0);
        float4 v3 = *(const float4*)(in1 + (rt + 3) * TP + k0);
#pragma unroll
        for (int kk = 0; kk < 4; kk++) {
            float4 wv = *(const float4*)(wS + ((k0 + kk) << 6) + jt);
            ull w0 = pk2(wv.x, wv.y), w1 = pk2(wv.z, wv.w);
            float s0 = kk == 0 ? u0.x : kk == 1 ? u0.y : kk == 2 ? u0.z : u0.w;
            float s1 = kk == 0 ? u1.x : kk == 1 ? u1.y : kk == 2 ? u1.z : u1.w;
            float s2 = kk == 0 ? u2.x : kk == 1 ? u2.y : kk == 2 ? u2.z : u2.w;
            float s3 = kk == 0 ? u3.x : kk == 1 ? u3.y : kk == 2 ? u3.z : u3.w;
            float t0 = kk == 0 ? v0.x : kk == 1 ? v0.y : kk == 2 ? v0.z : v0.w;
            float t1 = kk == 0 ? v1.x : kk == 1 ? v1.y : kk == 2 ? v1.z : v1.w;
            float t2 = kk == 0 ? v2.x : kk == 1 ? v2.y : kk == 2 ? v2.z : v2.w;
            float t3 = kk == 0 ? v3.x : kk == 1 ? v3.y : kk == 2 ? v3.z : v3.w;
            ull p;
            p = pk2(s0, s0); fma2(a0[0][0], p, w0); fma2(a0[0][1], p, w1);
            p = pk2(s1, s1); fma2(a0[1][0], p, w0); fma2(a0[1][1], p, w1);
            p = pk2(s2, s2); fma2(a0[2][0], p, w0); fma2(a0[2][1], p, w1);
            p = pk2(s3, s3); fma2(a0[3][0], p, w0); fma2(a0[3][1], p, w1);
            p = pk2(t0, t0); fma2(a1[0][0], p, w0); fma2(a1[0][1], p, w1);
            p = pk2(t1, t1); fma2(a1[1][0], p, w0); fma2(a1[1][1], p, w1);
            p = pk2(t2, t2); fma2(a1[2][0], p, w0); fma2(a1[2][1], p, w1);
            p = pk2(t3, t3); fma2(a1[3][0], p, w0); fma2(a1[3][1], p, w1);
        }
    }
}

// weight prefetch helpers
__device__ __forceinline__ void wload(const float* __restrict__ w, int t, float4 wr[4]) {
#pragma unroll
    for (int i = 0; i < 4; i++) wr[i] = ((const float4*)w)[t + i * 256];
}
__device__ __forceinline__ void wstore(float* ws, int t, const float4 wr[4]) {
#pragma unroll
    for (int i = 0; i < 4; i++) ((float4*)ws)[t + i * 256] = wr[i];
}

// ---------------- fused input MLP + xproj + inv-norm + dinv (PDL secondary) ------
#define SMEM_MLP_FLOATS 17152
__global__ void __launch_bounds__(256) k_mlp(
    const float* __restrict__ x,
    const float* __restrict__ w1, const float* __restrict__ b1,
    const float* __restrict__ w2, const float* __restrict__ b2,
    const float* __restrict__ w3, const float* __restrict__ b3,
    const float* __restrict__ wx, const float* __restrict__ bx) {
    extern __shared__ float sm[];
    float* wsA = sm;
    float* wsB = sm + 4096;
    float* bs  = sm + 8192;
    float* tA  = sm + 8448;
    float* tB  = sm + 12800;
    int t = threadIdx.x;
    const int jt = (t & 15) * 4;
    const int rt = (t >> 4) * 4;
    int n0 = blockIdx.x * 64;

    if (t < 64) { bs[t] = b1[t]; bs[64 + t] = b2[t]; bs[128 + t] = b3[t]; bs[192 + t] = bx[t]; }
    for (int i = t; i < 1024; i += 256) {
        int r = i >> 4, s4 = i & 15;
        int n = n0 + r;
        float4 v = (n < NN) ? *(const float4*)(x + n * 64 + s4 * 4) : make_float4(0, 0, 0, 0);
        *(float4*)(tA + r * TP + s4 * 4) = v;
        ((float4*)wsA)[i] = ((const float4*)w1)[i];
    }
    __syncthreads();

    ull acc[4][2];
    float4 wr[4];
    wload(w2, t, wr);
    gemm_core(tA, wsA, rt, jt, acc);
#pragma unroll
    for (int i = 0; i < 4; i++) {
        float2 p0 = upk(acc[i][0]), p1 = upk(acc[i][1]);
        tB[(rt + i) * TP + jt + 0] = fmaxf(p0.x + bs[jt + 0], 0.f);
        tB[(rt + i) * TP + jt + 1] = fmaxf(p0.y + bs[jt + 1], 0.f);
        tB[(rt + i) * TP + jt + 2] = fmaxf(p1.x + bs[jt + 2], 0.f);
        tB[(rt + i) * TP + jt + 3] = fmaxf(p1.y + bs[jt + 3], 0.f);
    }
    wstore(wsB, t, wr);
    __syncthreads();
    wload(w3, t, wr);
    gemm_core(tB, wsB, rt, jt, acc);
#pragma unroll
    for (int i = 0; i < 4; i++) {
        float2 p0 = upk(acc[i][0]), p1 = upk(acc[i][1]);
        tA[(rt + i) * TP + jt + 0] = fmaxf(p0.x + bs[64 + jt + 0], 0.f);
        tA[(rt + i) * TP + jt + 1] = fmaxf(p0.y + bs[64 + jt + 1], 0.f);
        tA[(rt + i) * TP + jt + 2] = fmaxf(p1.x + bs[64 + jt + 2], 0.f);
        tA[(rt + i) * TP + jt + 3] = fmaxf(p1.y + bs[64 + jt + 3], 0.f);
    }
    wstore(wsA, t, wr);
    __syncthreads();
    wload(wx, t, wr);
    gemm_core(tA, wsA, rt, jt, acc);
#pragma unroll
    for (int i = 0; i < 4; i++) {
        float2 p0 = upk(acc[i][0]), p1 = upk(acc[i][1]);
        float h0 = p0.x + bs[128 + jt + 0];
        float h1 = p0.y + bs[128 + jt + 1];
        float h2 = p1.x + bs[128 + jt + 2];
        float h3 = p1.y + bs[128 + jt + 3];
        tB[(rt + i) * TP + jt + 0] = h0;
        tB[(rt + i) * TP + jt + 1] = h1;
        tB[(rt + i) * TP + jt + 2] = h2;
        tB[(rt + i) * TP + jt + 3] = h3;
        int n = n0 + rt + i;
        if (n < NN) g_h4[n * 16 + (jt >> 2)] = make_float4(h0, h1, h2, h3);
    }
    wstore(wsB, t, wr);
    __syncthreads();
    // scatter must be complete before reading g_cnt
    cudaGridDependencySynchronize();
    if (t < 64) {
        int n = n0 + t;
        if (n < NN) {
            float ss = 0.f;
#pragma unroll 8
            for (int k = 0; k < 64; k++) { float v = tB[t * TP + k]; ss = fmaf(v, v, ss); }
            g_di[n] = make_float2(rsqrtf((float)(g_cnt[n] + 1)),
                                  1.f / (sqrtf(ss) + 1e-12f));
        }
    }
    gemm_core(tB, wsB, rt, jt, acc);
#pragma unroll
    for (int i = 0; i < 4; i++) {
        int n = n0 + rt + i;
        if (n < NN) {
            float2 p0 = upk(acc[i][0]), p1 = upk(acc[i][1]);
            g_xp4[n * 16 + (jt >> 2)] = make_float4(
                tanha(p0.x + bs[192 + jt + 0]), tanha(p0.y + bs[192 + jt + 1]),
                tanha(p1.x + bs[192 + jt + 2]), tanha(p1.y + bs[192 + jt + 3]));
        }
    }
}

// ---------------- CSR pull gather (PDL primary for k_final) ----------------
__global__ void __launch_bounds__(256) k_gather(const float* __restrict__ betap) {
    int warp = (blockIdx.x * 256 + threadIdx.x) >> 5;
    if (warp >= NN) { cudaTriggerProgrammaticLaunchCompletion(); return; }
    int c = warp;
    int lane = threadIdx.x & 31;
    int sub = lane >> 3;
    int sl  = lane & 7;
    float beta = *betap;
    float4 hc0 = g_h4[c * 16 + sl * 2];
    float4 hc1 = g_h4[c * 16 + sl * 2 + 1];
    float2 dic = g_di[c];

    float dps = hc0.x * hc0.x + hc0.y * hc0.y + hc0.z * hc0.z + hc0.w * hc0.w
              + hc1.x * hc1.x + hc1.y * hc1.y + hc1.z * hc1.z + hc1.w * hc1.w;
    dps += __shfl_xor_sync(0xFFFFFFFFu, dps, 1);
    dps += __shfl_xor_sync(0xFFFFFFFFu, dps, 2);
    dps += __shfl_xor_sync(0xFFFFFFFFu, dps, 4);
    float evs = __expf(beta * dps * dic.y * dic.y);
    float4 agg0, agg1, acc0, acc1;
    float s;
    if (sub == 0) {
        agg0 = make_float4(dic.x * hc0.x, dic.x * hc0.y, dic.x * hc0.z, dic.x * hc0.w);
        agg1 = make_float4(dic.x * hc1.x, dic.x * hc1.y, dic.x * hc1.z, dic.x * hc1.w);
        acc0 = make_float4(evs * hc0.x, evs * hc0.y, evs * hc0.z, evs * hc0.w);
        acc1 = make_float4(evs * hc1.x, evs * hc1.y, evs * hc1.z, evs * hc1.w);
        s = evs;
    } else {
        agg0 = agg1 = acc0 = acc1 = make_float4(0.f, 0.f, 0.f, 0.f);
        s = 0.f;
    }

    int beg = c << 6;
    int cnt = min(g_cnt[c], DCAP);
    int T = (cnt + 3) >> 2;
    bool v0 = (sub < cnt);
    int r0 = v0 ? g_csr[beg + sub] : c;
    float4 a0 = g_h4[r0 * 16 + sl * 2];
    float4 b0 = g_h4[r0 * 16 + sl * 2 + 1];
    float2 d0 = g_di[r0];
    for (int it = 0; it < T; it++) {
        int nx = 4 * (it + 1) + sub;
        bool vn = (nx < cnt);
        int rn = vn ? g_csr[beg + nx] : c;
        float4 an = g_h4[rn * 16 + sl * 2];
        float4 bn = g_h4[rn * 16 + sl * 2 + 1];
        float2 dn = g_di[rn];

        float dp = a0.x * hc0.x + a0.y * hc0.y + a0.z * hc0.z + a0.w * hc0.w
                 + b0.x * hc1.x + b0.y * hc1.y + b0.z * hc1.z + b0.w * hc1.w;
        dp += __shfl_xor_sync(0xFFFFFFFFu, dp, 1);
        dp += __shfl_xor_sync(0xFFFFFFFFu, dp, 2);
        dp += __shfl_xor_sync(0xFFFFFFFFu, dp, 4);
        float ev = v0 ? __expf(beta * dp * d0.y * dic.y) : 0.f;
        float w  = v0 ? d0.x : 0.f;
        agg0.x = fmaf(w, a0.x, agg0.x); agg0.y = fmaf(w, a0.y, agg0.y);
        agg0.z = fmaf(w, a0.z, agg0.z); agg0.w = fmaf(w, a0.w, agg0.w);
        agg1.x = fmaf(w, b0.x, agg1.x); agg1.y = fmaf(w, b0.y, agg1.y);
        agg1.z = fmaf(w, b0.z, agg1.z); agg1.w = fmaf(w, b0.w, agg1.w);
        acc0.x = fmaf(ev, a0.x, acc0.x); acc0.y = fmaf(ev, a0.y, acc0.y);
        acc0.z = fmaf(ev, a0.z, acc0.z); acc0.w = fmaf(ev, a0.w, acc0.w);
        acc1.x = fmaf(ev, b0.x, acc1.x); acc1.y = fmaf(ev, b0.y, acc1.y);
        acc1.z = fmaf(ev, b0.z, acc1.z); acc1.w = fmaf(ev, b0.w, acc1.w);
        s += ev;
        v0 = vn; r0 = rn; a0 = an; b0 = bn; d0 = dn;
    }
#pragma unroll
    for (int d = 8; d <= 16; d <<= 1) {
        agg0.x += __shfl_xor_sync(0xFFFFFFFFu, agg0.x, d);
        agg0.y += __shfl_xor_sync(0xFFFFFFFFu, agg0.y, d);
        agg0.z += __shfl_xor_sync(0xFFFFFFFFu, agg0.z, d);
        agg0.w += __shfl_xor_sync(0xFFFFFFFFu, agg0.w, d);
        agg1.x += __shfl_xor_sync(0xFFFFFFFFu, agg1.x, d);
        agg1.y += __shfl_xor_sync(0xFFFFFFFFu, agg1.y, d);
        agg1.z += __shfl_xor_sync(0xFFFFFFFFu, agg1.z, d);
        agg1.w += __shfl_xor_sync(0xFFFFFFFFu, agg1.w, d);
        acc0.x += __shfl_xor_sync(0xFFFFFFFFu, acc0.x, d);
        acc0.y += __shfl_xor_sync(0xFFFFFFFFu, acc0.y, d);
        acc0.z += __shfl_xor_sync(0xFFFFFFFFu, acc0.z, d);
        acc0.w += __shfl_xor_sync(0xFFFFFFFFu, acc0.w, d);
        acc1.x += __shfl_xor_sync(0xFFFFFFFFu, acc1.x, d);
        acc1.y += __shfl_xor_sync(0xFFFFFFFFu, acc1.y, d);
        acc1.z += __shfl_xor_sync(0xFFFFFFFFu, acc1.z, d);
        acc1.w += __shfl_xor_sync(0xFFFFFFFFu, acc1.w, d);
        s += __shfl_xor_sync(0xFFFFFFFFu, s, d);
    }
    if (sub == 0) {
        float invs = 1.f / s;
        g_agg4[c * 16 + sl * 2] = make_float4(dic.x * agg0.x, dic.x * agg0.y, dic.x * agg0.z, dic.x * agg0.w);
        g_agg4[c * 16 + sl * 2 + 1] = make_float4(dic.x * agg1.x, dic.x * agg1.y, dic.x * agg1.z, dic.x * agg1.w);
        g_acc4[c * 16 + sl * 2] = make_float4(invs * acc0.x, invs * acc0.y, invs * acc0.z, invs * acc0.w);
        g_acc4[c * 16 + sl * 2 + 1] = make_float4(invs * acc1.x, invs * acc1.y, invs * acc1.z, invs * acc1.w);
    }
    if (lane == 0) g_cnt[c] = 0;
    cudaTriggerProgrammaticLaunchCompletion();
}

// ---------------- fused filters + attention fusion + classifier (PDL secondary) --
#define SMEM_FIN_FLOATS 21704
__global__ void __launch_bounds__(256) k_final(
    const float* __restrict__ wg1, const float* __restrict__ bg1,
    const float* __restrict__ wg2, const float* __restrict__ bg2,
    const float* __restrict__ wf,  const float* __restrict__ bf,
    const float* __restrict__ wc,  const float* __restrict__ bc,
    float* __restrict__ out) {
    extern __shared__ float sm[];
    float* wsA  = sm;
    float* wsB  = sm + 4096;
    float* wcs  = sm + 8192;
    float* bs   = sm + 8448;
    float* aggS = sm + 8648;
    float* f0S  = sm + 13000;
    float* f1S  = sm + 17352;
    int t = threadIdx.x;
    const int jt = (t & 15) * 4;
    const int rt = (t >> 4) * 4;
    int n0 = blockIdx.x * 64;

    // stage everything that does NOT depend on k_gather first
    if (t < 256) wcs[t] = wc[t];
    if (t < 64) { bs[t] = bg1[t]; bs[64 + t] = bg2[t]; bs[128 + t] = bf[t]; }
    if (t < 2) bs[192 + t] = bc[t];
    for (int i = t; i < 1024; i += 256) {
        ((float4*)wsA)[i] = ((const float4*)wg1)[i];
        ((float4*)wsB)[i] = ((const float4*)wg2)[i];
    }
    // now wait for gather's outputs
    cudaGridDependencySynchronize();
    const float* agg = (const float*)g_agg4;
    for (int i = t; i < 1024; i += 256) {
        int r = i >> 4, s4 = i & 15;
        int n = n0 + r;
        float4 v = (n < NN) ? *(const float4*)(agg + n * 64 + s4 * 4) : make_float4(0, 0, 0, 0);
        *(float4*)(aggS + r * TP + s4 * 4) = v;
    }
    __syncthreads();

    ull a0[4][2], a1[4][2];
    float4 wr[4];
    float2 f0r[4][2], f1r[4][2];
    wload(wf, t, wr);
    gemm_core_w2(aggS, wsA, wsB, rt, jt, a0, a1);
    __syncthreads();
#pragma unroll
    for (int i = 0; i < 4; i++) {
        float2 p0 = upk(a0[i][0]), p1 = upk(a0[i][1]);
        float2 q0 = upk(a1[i][0]), q1 = upk(a1[i][1]);
        f0r[i][0] = make_float2(p0.x + bs[jt + 0], p0.y + bs[jt + 1]);
        f0r[i][1] = make_float2(p1.x + bs[jt + 2], p1.y + bs[jt + 3]);
        f1r[i][0] = make_float2(q0.x + bs[64 + jt + 0], q0.y + bs[64 + jt + 1]);
        f1r[i][1] = make_float2(q1.x + bs[64 + jt + 2], q1.y + bs[64 + jt + 3]);
        f0S[(rt + i) * TP + jt + 0] = f0r[i][0].x;
        f0S[(rt + i) * TP + jt + 1] = f0r[i][0].y;
        f0S[(rt + i) * TP + jt + 2] = f0r[i][1].x;
        f0S[(rt + i) * TP + jt + 3] = f0r[i][1].y;
        f1S[(rt + i) * TP + jt + 0] = f1r[i][0].x;
        f1S[(rt + i) * TP + jt + 1] = f1r[i][0].y;
        f1S[(rt + i) * TP + jt + 2] = f1r[i][1].x;
        f1S[(rt + i) * TP + jt + 3] = f1r[i][1].y;
    }
    wstore(wsA, t, wr);
    __syncthreads();
    gemm_core2(f0S, f1S, wsA, rt, jt, a0, a1);
    float p0a[4], p1a[4];
    const float* xp = (const float*)g_xp4;
#pragma unroll
    for (int i = 0; i < 4; i++) {
        int n = n0 + rt + i;
        float4 xv = (n < NN) ? *(const float4*)(xp + n * 64 + jt) : make_float4(0, 0, 0, 0);
        float2 q0 = upk(a0[i][0]), q1 = upk(a0[i][1]);
        float2 r0 = upk(a1[i][0]), r1 = upk(a1[i][1]);
        float h00 = tanha(q0.x + bs[128 + jt + 0]);
        float h01 = tanha(q0.y + bs[128 + jt + 1]);
        float h02 = tanha(q1.x + bs[128 + jt + 2]);
        float h03 = tanha(q1.y + bs[128 + jt + 3]);
        float h10 = tanha(r0.x + bs[128 + jt + 0]);
        float h11 = tanha(r0.y + bs[128 + jt + 1]);
        float h12 = tanha(r1.x + bs[128 + jt + 2]);
        float h13 = tanha(r1.y + bs[128 + jt + 3]);
        p0a[i] = h00 * xv.x + h01 * xv.y + h02 * xv.z + h03 * xv.w;
        p1a[i] = h10 * xv.x + h11 * xv.y + h12 * xv.z + h13 * xv.w;
    }
#pragma unroll
    for (int d = 1; d <= 8; d <<= 1) {
#pragma unroll
        for (int i = 0; i < 4; i++) {
            p0a[i] += __shfl_xor_sync(0xFFFFFFFFu, p0a[i], d);
            p1a[i] += __shfl_xor_sync(0xFFFFFFFFu, p1a[i], d);
        }
    }
    float sc0r[4], sc1r[4];
#pragma unroll
    for (int i = 0; i < 4; i++) {
        float mx = fmaxf(p0a[i], p1a[i]);
        float e0 = __expf(p0a[i] - mx), e1 = __expf(p1a[i] - mx);
        float inv = 1.f / (e0 + e1);
        sc0r[i] = e0 * inv;
        sc1r[i] = e1 * inv;
    }
    const float* acc1g = (const float*)g_acc4;
    float y0[4], y1[4];
#pragma unroll
    for (int i = 0; i < 4; i++) {
        int n = n0 + rt + i;
        y0[i] = 0.f; y1[i] = 0.f;
        if (n < NN) {
            float4 hv = *(const float4*)(acc1g + n * 64 + jt);
            float fr[4] = {
                sc0r[i] * f0r[i][0].x + sc1r[i] * f1r[i][0].x,
                sc0r[i] * f0r[i][0].y + sc1r[i] * f1r[i][0].y,
                sc0r[i] * f0r[i][1].x + sc1r[i] * f1r[i][1].x,
                sc0r[i] * f0r[i][1].y + sc1r[i] * f1r[i][1].y };
            float h1v[4] = {hv.x, hv.y, hv.z, hv.w};
#pragma unroll
            for (int q = 0; q < 4; q++) {
                int j = jt + q;
                y0[i] += fr[q] * wcs[j * 2 + 0] + h1v[q] * wcs[(64 + j) * 2 + 0];
                y1[i] += fr[q] * wcs[j * 2 + 1] + h1v[q] * wcs[(64 + j) * 2 + 1];
            }
        }
    }
#pragma unroll
    for (int d = 1; d <= 8; d <<= 1) {
#pragma unroll
        for (int i = 0; i < 4; i++) {
            y0[i] += __shfl_xor_sync(0xFFFFFFFFu, y0[i], d);
            y1[i] += __shfl_xor_sync(0xFFFFFFFFu, y1[i], d);
        }
    }
    if ((t & 15) == 0) {
#pragma unroll
        for (int i = 0; i < 4; i++) {
            int n = n0 + rt + i;
            if (n < NN) {
                out[n * 2 + 0] = y0[i] + bs[192];
                out[n * 2 + 1] = y1[i] + bs[193];
            }
        }
    }
}

// ---------------- launch: 4 kernels, PDL edges scatter->mlp and gather->final ----
extern "C" void kernel_launch(void* const* d_in, const int* in_sizes, int n_in,
                              void* d_out, int out_size) {
    const float* x   = (const float*)d_in[0];
    const int*   ei  = (const int*)d_in[1];
    const float* w1  = (const float*)d_in[2];
    const float* b1  = (const float*)d_in[3];
    const float* w2  = (const float*)d_in[4];
    const float* b2  = (const float*)d_in[5];
    const float* w3  = (const float*)d_in[6];
    const float* b3  = (const float*)d_in[7];
    const float* wg1 = (const float*)d_in[8];
    const float* bg1 = (const float*)d_in[9];
    const float* wg2 = (const float*)d_in[10];
    const float* bg2 = (const float*)d_in[11];
    const float* beta= (const float*)d_in[12];
    const float* wf  = (const float*)d_in[13];
    const float* bf  = (const float*)d_in[14];
    const float* wx  = (const float*)d_in[15];
    const float* bx  = (const float*)d_in[16];
    const float* wc  = (const float*)d_in[17];
    const float* bc  = (const float*)d_in[18];
    float* out = (float*)d_out;

    cudaFuncSetAttribute(k_mlp,   cudaFuncAttributeMaxDynamicSharedMemorySize, SMEM_MLP_FLOATS * 4);
    cudaFuncSetAttribute(k_final, cudaFuncAttributeMaxDynamicSharedMemorySize, SMEM_FIN_FLOATS * 4);

    cudaLaunchAttribute pdl[1];
    pdl[0].id = cudaLaunchAttributeProgrammaticStreamSerialization;
    pdl[0].val.programmaticStreamSerializationAllowed = 1;

    k_scatter<<<(EE + 255) / 256, 256>>>(ei);

    {   // k_mlp: starts while scatter drains; grid-syncs before reading g_cnt
        cudaLaunchConfig_t cfg = {};
        cfg.gridDim = dim3((NN + 63) / 64, 1, 1);
        cfg.blockDim = dim3(256, 1, 1);
        cfg.dynamicSmemBytes = SMEM_MLP_FLOATS * 4;
        cfg.stream = 0;
        cfg.attrs = pdl;
        cfg.numAttrs = 1;
        cudaLaunchKernelEx(&cfg, k_mlp, x, w1, b1, w2, b2, w3, b3, wx, bx);
    }

    k_gather<<<(NN * 32 + 255) / 256, 256>>>(beta);

    {   // k_final: stages weights early; grid-syncs before reading g_agg4/g_acc4
        cudaLaunchConfig_t cfg = {};
        cfg.gridDim = dim3((NN + 63) / 64, 1, 1);
        cfg.blockDim = dim3(256, 1, 1);
        cfg.dynamicSmemBytes = SMEM_FIN_FLOATS * 4;
        cfg.stream = 0;
        cfg.attrs = pdl;
        cfg.numAttrs = 1;
        cudaLaunchKernelEx(&cfg, k_final, wg1, bg1, wg2, bg2, wf, bf, wc, bc, out);
    }
}